// round 7
// baseline (speedup 1.0000x reference)
#include <cuda_runtime.h>
#include <cstdint>

// SGIntoKGPool via tf32 mma.sync (m16n8k8, base PTX, safe on compute_103).
// out[b,m,c] = (sum_n adj[b,n,m] * x[b,c,n]) / max(sum_n adj[b,n,m], 1)
// B=8, C=64, N=4096, M=2048.
// Round 7: cp.async 4-stage fp32 ring for adj (zero conversion, deep MLP),
// B fragments via conflict-free LDS.32, A fragments (x, tf32-rounded) direct
// from L2-resident panels, degrees fused from B fragment registers.

#define BZv 8
#define Cv  64
#define Nv  4096
#define Mv  2048
#define KT  32
#define NTl (Nv / KT)       // 128 k-tiles
#define MTm 64              // m-tile
#define DEPTH 4

#define TSTRIDE 288          // bytes per smem B row (72 floats: 64 + 8 pad)
#define TILEB   (KT * TSTRIDE)              // 9216
#define OFF_DEGS (DEPTH * TILEB)            // 36864
#define OFF_INVS (OFF_DEGS + 256)           // 37120
#define SMEMB    (OFF_INVS + 256)           // 37376

// x tf32 fragment panels: per (b,kt): 16 groups (cblk*4+kb) x 32 lanes x uint4 = 8KB
__device__ uint4 g_A[BZv * NTl * 512];      // 8 MB

__device__ __forceinline__ uint32_t smem_u32(const void* p) {
    uint32_t a;
    asm("{ .reg .u64 t; cvta.to.shared.u64 t, %1; cvt.u32.u64 %0, t; }" : "=r"(a) : "l"(p));
    return a;
}
__device__ __forceinline__ void cp16(uint32_t saddr, const void* gaddr) {
    asm volatile("cp.async.cg.shared.global [%0], [%1], 16;" :: "r"(saddr), "l"(gaddr));
}
__device__ __forceinline__ uint32_t lds32(uint32_t a) {
    uint32_t v;
    asm volatile("ld.shared.b32 %0, [%1];" : "=r"(v) : "r"(a));
    return v;
}
__device__ __forceinline__ void mma_tf32(float (&d)[4], const uint4& a,
                                         uint32_t b0, uint32_t b1) {
    asm volatile("mma.sync.aligned.m16n8k8.row.col.f32.tf32.tf32.f32 "
                 "{%0,%1,%2,%3}, {%4,%5,%6,%7}, {%8,%9}, {%0,%1,%2,%3};"
                 : "+f"(d[0]), "+f"(d[1]), "+f"(d[2]), "+f"(d[3])
                 : "r"(a.x), "r"(a.y), "r"(a.z), "r"(a.w), "r"(b0), "r"(b1));
}
__device__ __forceinline__ uint32_t f2tf32(float v) {
    uint32_t r;
    asm("cvt.rna.tf32.f32 %0, %1;" : "=r"(r) : "f"(v));
    return r;
}

// ---------------- prep: x -> tf32 fragment panels ----------------
// thread <-> (b, kt, cblk, kb, lid): 8*128*4*4... groups = cblk*4+kb (16), 32 lanes
__global__ __launch_bounds__(256)
void prep_A(const float* __restrict__ x) {
    unsigned gid  = blockIdx.x * 256 + threadIdx.x;     // 524288 threads
    unsigned lid  = gid & 31;
    unsigned kb   = (gid >> 5) & 3;
    unsigned cblk = (gid >> 7) & 3;
    unsigned kt   = (gid >> 9) & (NTl - 1);
    unsigned b    = gid >> 16;

    int r0 = cblk * 16 + (lid >> 2);        // c row (0..63)
    int k0 = kb * 8 + (lid & 3);            // k within tile
    const float* px = x + ((size_t)b * Cv + r0) * Nv + kt * KT + k0;

    uint4 f;
    f.x = f2tf32(px[0]);            // (r0,   k0)
    f.y = f2tf32(px[8 * Nv]);       // (r0+8, k0)
    f.z = f2tf32(px[4]);            // (r0,   k0+4)
    f.w = f2tf32(px[8 * Nv + 4]);   // (r0+8, k0+4)

    g_A[(size_t)((b * NTl + kt) * 16 + cblk * 4 + kb) * 32 + lid] = f;
}

// ---------------- main kernel ----------------
__global__ __launch_bounds__(256, 2)
void sg_kg_tf32(const float* __restrict__ adj, float* __restrict__ out) {
    __shared__ __align__(16) char smem[SMEMB];
    const int tid = threadIdx.x;
    const int lid = tid & 31, wid = tid >> 5;
    const int b = blockIdx.y, m0 = blockIdx.x * MTm;
    const int wr = wid & 1;          // c dir: 2 warps x 32 rows
    const int wc = wid >> 1;         // m dir: 4 warps x 16 cols
    const uint32_t sb = smem_u32(smem);

    // cp.async lane mapping: thread owns (k-row, two 16B m-chunks)
    const int kcp  = tid >> 3;       // 0..31
    const int c16a = tid & 7;        // chunks c16a and c16a+8
    const float* adjb = adj + (size_t)b * Nv * Mv + m0;
    const uint32_t scp = sb + kcp * TSTRIDE + c16a * 16;

    auto issue = [&](int t) {
        const float* g = adjb + (size_t)(t * KT + kcp) * Mv + c16a * 4;
        uint32_t s = scp + (t & (DEPTH - 1)) * TILEB;
        cp16(s, g);
        cp16(s + 128, g + 32);
        asm volatile("cp.async.commit_group;" ::: "memory");
    };

    float acc[2][2][4];
    #pragma unroll
    for (int i = 0; i < 2; i++)
        #pragma unroll
        for (int j = 0; j < 2; j++)
            #pragma unroll
            for (int p = 0; p < 4; p++) acc[i][j][p] = 0.f;
    float dacc0 = 0.f, dacc1 = 0.f;

    // B fragment base: b0 = B[k = kb*8 + (lid&3)][m = wc*16 + nb*8 + (lid>>2)]
    const uint32_t bbase = sb + (lid & 3) * TSTRIDE + (wc * 16 + (lid >> 2)) * 4;
    const uint4* Abase = g_A + (size_t)(b * NTl) * 512 + lid;

    // prologue: stages 0..2
    issue(0); issue(1); issue(2);

    for (int t = 0; t < NTl; t++) {
        asm volatile("cp.async.wait_group 2;" ::: "memory");
        __syncthreads();

        // A fragments for this tile (L2-resident, 8 x LDG.128)
        const uint4* At = Abase + (size_t)t * 512;
        uint4 af[2][4];
        #pragma unroll
        for (int ci = 0; ci < 2; ci++)
            #pragma unroll
            for (int kb = 0; kb < 4; kb++)
                af[ci][kb] = At[((wr * 2 + ci) * 4 + kb) * 32];

        const uint32_t bufo = (t & (DEPTH - 1)) * TILEB;
        #pragma unroll
        for (int kb = 0; kb < 4; kb++) {
            const uint32_t ba = bbase + bufo + kb * (8 * TSTRIDE);
            uint32_t b00 = lds32(ba);                        // nb=0, k
            uint32_t b01 = lds32(ba + 4 * TSTRIDE);          // nb=0, k+4
            uint32_t b10 = lds32(ba + 32);                   // nb=1, k
            uint32_t b11 = lds32(ba + 32 + 4 * TSTRIDE);     // nb=1, k+4
            if (wr == 0) {   // degree accumulate (raw fp32, exact)
                dacc0 += __uint_as_float(b00) + __uint_as_float(b01);
                dacc1 += __uint_as_float(b10) + __uint_as_float(b11);
            }
            mma_tf32(acc[0][0], af[0][kb], b00, b01);
            mma_tf32(acc[0][1], af[0][kb], b10, b11);
            mma_tf32(acc[1][0], af[1][kb], b00, b01);
            mma_tf32(acc[1][1], af[1][kb], b10, b11);
        }

        if (t + 3 < NTl) issue(t + 3);
    }

    // ---- degree reduction: sum over the 4 k-lanes sharing each n ----
    float* degS = (float*)(smem + OFF_DEGS);
    float* invS = (float*)(smem + OFF_INVS);
    #pragma unroll
    for (int s = 1; s <= 2; s <<= 1) {
        dacc0 += __shfl_xor_sync(0xffffffffu, dacc0, s);
        dacc1 += __shfl_xor_sync(0xffffffffu, dacc1, s);
    }
    if (wr == 0 && (lid & 3) == 0) {
        degS[wc * 16 + (lid >> 2)]     = dacc0;
        degS[wc * 16 + 8 + (lid >> 2)] = dacc1;
    }
    __syncthreads();
    if (tid < MTm) invS[tid] = 1.0f / fmaxf(degS[tid], 1.0f);

    // ---- stage accumulators to smem (aliases ring; all consumption done) ----
    float* outS = (float*)smem;   // [m][c], stride 68 floats (17408 B <= ring)
    #pragma unroll
    for (int ci = 0; ci < 2; ci++) {
        #pragma unroll
        for (int nb = 0; nb < 2; nb++) {
            int c_row = wr * 32 + ci * 16 + (lid >> 2);
            int m_col = wc * 16 + nb * 8 + (lid & 3) * 2;
            outS[m_col * 68 + c_row]           = acc[ci][nb][0];
            outS[(m_col + 1) * 68 + c_row]     = acc[ci][nb][1];
            outS[m_col * 68 + c_row + 8]       = acc[ci][nb][2];
            outS[(m_col + 1) * 68 + c_row + 8] = acc[ci][nb][3];
        }
    }
    __syncthreads();

    // ---- scaled float4 stores ----
    float* Og = out + ((size_t)b * Mv + m0) * Cv;
    #pragma unroll
    for (int i = 0; i < 4; i++) {
        int idx = tid + i * 256;                 // 1024 float4s
        int ml = idx >> 4, c4 = (idx & 15) * 4;
        float4 v = *(float4*)(outS + ml * 68 + c4);
        float inv = invS[ml];
        v.x *= inv; v.y *= inv; v.z *= inv; v.w *= inv;
        *(float4*)(Og + (size_t)ml * Cv + c4) = v;
    }
}

extern "C" void kernel_launch(void* const* d_in, const int* in_sizes, int n_in,
                              void* d_out, int out_size)
{
    const float* x;
    const float* adj;
    if (in_sizes[0] == BZv * Cv * Nv) {
        x   = (const float*)d_in[0];
        adj = (const float*)d_in[1];
    } else {
        x   = (const float*)d_in[1];
        adj = (const float*)d_in[0];
    }
    float* out = (float*)d_out;

    prep_A<<<2048, 256>>>(x);                                // 524288 threads
    sg_kg_tf32<<<dim3(Mv / MTm, BZv), 256>>>(adj, out);      // 32 x 8 = 256 CTAs
}

// round 8
// speedup vs baseline: 1.3386x; 1.3386x over previous
#include <cuda_runtime.h>
#include <cstdint>

// SGIntoKGPool via tf32 mma.sync (m16n8k8, base PTX, safe on compute_103).
// out[b,m,c] = (sum_n adj[b,n,m] * x[b,c,n]) / max(sum_n adj[b,n,m], 1)
// B=8, C=64, N=4096, M=2048.
// Round 8: KT=64 (64 tiles, half the barrier/wait count), exact cp.async waits,
// A fragments in a rolling 4-slot register ring loaded ahead of use (L2 latency
// off the critical path). Degrees fused from B fragment registers.

#define BZv 8
#define Cv  64
#define Nv  4096
#define Mv  2048
#define KT  64
#define NTl (Nv / KT)       // 64 k-tiles
#define MTm 64              // m-tile

#define TSTRIDE 288          // bytes per smem B row (72 floats: 64 + 8 pad)
#define TILEB   (KT * TSTRIDE)              // 18432
#define OFF_DEGS (2 * TILEB)                // 36864
#define OFF_INVS (OFF_DEGS + 256)           // 37120
#define SMEMB    (OFF_INVS + 256)           // 37376

// x tf32 fragment panels: per (b,kt): 32 groups (cblk*8+kb) x 32 lanes x uint4 = 16KB
__device__ uint4 g_A[BZv * NTl * 1024];     // 8 MB

__device__ __forceinline__ uint32_t smem_u32(const void* p) {
    uint32_t a;
    asm("{ .reg .u64 t; cvta.to.shared.u64 t, %1; cvt.u32.u64 %0, t; }" : "=r"(a) : "l"(p));
    return a;
}
__device__ __forceinline__ void cp16(uint32_t saddr, const void* gaddr) {
    asm volatile("cp.async.cg.shared.global [%0], [%1], 16;" :: "r"(saddr), "l"(gaddr));
}
__device__ __forceinline__ uint32_t lds32(uint32_t a) {
    uint32_t v;
    asm volatile("ld.shared.b32 %0, [%1];" : "=r"(v) : "r"(a));
    return v;
}
__device__ __forceinline__ void mma_tf32(float (&d)[4], const uint4& a,
                                         uint32_t b0, uint32_t b1) {
    asm volatile("mma.sync.aligned.m16n8k8.row.col.f32.tf32.tf32.f32 "
                 "{%0,%1,%2,%3}, {%4,%5,%6,%7}, {%8,%9}, {%0,%1,%2,%3};"
                 : "+f"(d[0]), "+f"(d[1]), "+f"(d[2]), "+f"(d[3])
                 : "r"(a.x), "r"(a.y), "r"(a.z), "r"(a.w), "r"(b0), "r"(b1));
}
__device__ __forceinline__ uint32_t f2tf32(float v) {
    uint32_t r;
    asm("cvt.rna.tf32.f32 %0, %1;" : "=r"(r) : "f"(v));
    return r;
}

// ---------------- prep: x -> tf32 fragment panels ----------------
// thread <-> (b, kt, cblk, kb, lid): 8 * 64 * 4 * 8 * 32 = 524288 threads
__global__ __launch_bounds__(256)
void prep_A(const float* __restrict__ x) {
    unsigned gid  = blockIdx.x * 256 + threadIdx.x;
    unsigned lid  = gid & 31;
    unsigned kb   = (gid >> 5) & 7;
    unsigned cblk = (gid >> 8) & 3;
    unsigned kt   = (gid >> 10) & (NTl - 1);
    unsigned b    = gid >> 16;

    int r0 = cblk * 16 + (lid >> 2);        // c row (0..63)
    int k0 = kb * 8 + (lid & 3);            // k within tile
    const float* px = x + ((size_t)b * Cv + r0) * Nv + kt * KT + k0;

    uint4 f;
    f.x = f2tf32(px[0]);            // (r0,   k0)
    f.y = f2tf32(px[8 * Nv]);       // (r0+8, k0)
    f.z = f2tf32(px[4]);            // (r0,   k0+4)
    f.w = f2tf32(px[8 * Nv + 4]);   // (r0+8, k0+4)

    g_A[((size_t)(b * NTl + kt) << 10) + (cblk * 8 + kb) * 32 + lid] = f;
}

// ---------------- main kernel ----------------
__global__ __launch_bounds__(256, 2)
void sg_kg_tf32(const float* __restrict__ adj, float* __restrict__ out) {
    __shared__ __align__(16) char smem[SMEMB];
    const int tid = threadIdx.x;
    const int lid = tid & 31, wid = tid >> 5;
    const int b = blockIdx.y, m0 = blockIdx.x * MTm;
    const int wr = wid & 1;          // c dir: 2 warps x 32 rows
    const int wc = wid >> 1;         // m dir: 4 warps x 16 cols
    const uint32_t sb = smem_u32(smem);

    // cp.async lane mapping: thread owns k-row kcp, four 16B chunks of its 256B row part
    const int kcp = tid >> 2;        // 0..63
    const int c16 = tid & 3;         // chunk group
    const float* adjb = adj + (size_t)b * Nv * Mv + m0;
    const uint32_t scp = sb + kcp * TSTRIDE + c16 * 16;

    auto issue = [&](int t) {
        const float* g = adjb + (size_t)(t * KT + kcp) * Mv + c16 * 4;
        uint32_t s = scp + (t & 1) * TILEB;
        cp16(s, g);
        cp16(s + 64, g + 16);
        cp16(s + 128, g + 32);
        cp16(s + 192, g + 48);
        asm volatile("cp.async.commit_group;" ::: "memory");
    };

    float acc[2][2][4];
    #pragma unroll
    for (int i = 0; i < 2; i++)
        #pragma unroll
        for (int j = 0; j < 2; j++)
            #pragma unroll
            for (int p = 0; p < 4; p++) acc[i][j][p] = 0.f;
    float dacc0 = 0.f, dacc1 = 0.f;

    // B fragment base: B[k = kb*8 + (lid&3)][m = wc*16 + nb*8 + (lid>>2)]
    const uint32_t bbase = sb + (lid & 3) * TSTRIDE + (wc * 16 + (lid >> 2)) * 4;
    const uint4* Apanels = g_A + ((size_t)(b * NTl) << 10) + lid;
    const int g0 = (wr * 2 + 0) * 8 * 32;     // cblk group base (uint4 units)
    const int g1 = (wr * 2 + 1) * 8 * 32;

    // rolling A-fragment ring: 4 kb-slots x 2 cblk
    uint4 afr[4][2];
    {
        const uint4* A0 = Apanels;            // tile 0
        #pragma unroll
        for (int s = 0; s < 4; s++) {
            afr[s][0] = A0[g0 + s * 32];
            afr[s][1] = A0[g1 + s * 32];
        }
    }

    // prologue: stages 0,1 in flight
    issue(0); issue(1);

    for (int t = 0; t < NTl; t++) {
        if (t == NTl - 1) asm volatile("cp.async.wait_group 0;" ::: "memory");
        else              asm volatile("cp.async.wait_group 1;" ::: "memory");
        __syncthreads();

        const uint4* Acur  = Apanels + ((size_t)t << 10);
        const uint4* Anext = Apanels + ((size_t)((t + 1 < NTl) ? t + 1 : t) << 10);
        const uint32_t bufo = (t & 1) * TILEB;

        #pragma unroll
        for (int kb = 0; kb < 8; kb++) {
            const int slot = kb & 3;
            const uint32_t ba = bbase + bufo + kb * (8 * TSTRIDE);
            uint32_t b00 = lds32(ba);                        // nb=0, k
            uint32_t b01 = lds32(ba + 4 * TSTRIDE);          // nb=0, k+4
            uint32_t b10 = lds32(ba + 32);                   // nb=1, k
            uint32_t b11 = lds32(ba + 32 + 4 * TSTRIDE);     // nb=1, k+4
            if (wr == 0) {   // degree accumulate (raw fp32, exact)
                dacc0 += __uint_as_float(b00) + __uint_as_float(b01);
                dacc1 += __uint_as_float(b10) + __uint_as_float(b11);
            }
            mma_tf32(acc[0][0], afr[slot][0], b00, b01);
            mma_tf32(acc[0][1], afr[slot][0], b10, b11);
            mma_tf32(acc[1][0], afr[slot][1], b00, b01);
            mma_tf32(acc[1][1], afr[slot][1], b10, b11);
            // refill slot: kb+4 of this tile, or kb-4 of next tile
            const uint4* Asrc = (kb < 4) ? Acur : Anext;
            const int kk = (kb < 4) ? kb + 4 : kb - 4;
            afr[slot][0] = Asrc[g0 + kk * 32];
            afr[slot][1] = Asrc[g1 + kk * 32];
        }

        __syncthreads();                    // all reads of buf (t&1) done
        if (t + 2 < NTl) issue(t + 2);      // safe to overwrite it now
    }

    // ---- degree reduction: sum over the 4 k-lanes sharing each n ----
    float* degS = (float*)(smem + OFF_DEGS);
    float* invS = (float*)(smem + OFF_INVS);
    #pragma unroll
    for (int s = 1; s <= 2; s <<= 1) {
        dacc0 += __shfl_xor_sync(0xffffffffu, dacc0, s);
        dacc1 += __shfl_xor_sync(0xffffffffu, dacc1, s);
    }
    if (wr == 0 && (lid & 3) == 0) {
        degS[wc * 16 + (lid >> 2)]     = dacc0;
        degS[wc * 16 + 8 + (lid >> 2)] = dacc1;
    }
    __syncthreads();
    if (tid < MTm) invS[tid] = 1.0f / fmaxf(degS[tid], 1.0f);

    // ---- stage accumulators to smem (aliases ring; all consumption done) ----
    float* outS = (float*)smem;   // [m][c], stride 68 floats (17408 B <= ring)
    #pragma unroll
    for (int ci = 0; ci < 2; ci++) {
        #pragma unroll
        for (int nb = 0; nb < 2; nb++) {
            int c_row = wr * 32 + ci * 16 + (lid >> 2);
            int m_col = wc * 16 + nb * 8 + (lid & 3) * 2;
            outS[m_col * 68 + c_row]           = acc[ci][nb][0];
            outS[(m_col + 1) * 68 + c_row]     = acc[ci][nb][1];
            outS[m_col * 68 + c_row + 8]       = acc[ci][nb][2];
            outS[(m_col + 1) * 68 + c_row + 8] = acc[ci][nb][3];
        }
    }
    __syncthreads();

    // ---- scaled float4 stores ----
    float* Og = out + ((size_t)b * Mv + m0) * Cv;
    #pragma unroll
    for (int i = 0; i < 4; i++) {
        int idx = tid + i * 256;                 // 1024 float4s
        int ml = idx >> 4, c4 = (idx & 15) * 4;
        float4 v = *(float4*)(outS + ml * 68 + c4);
        float inv = invS[ml];
        v.x *= inv; v.y *= inv; v.z *= inv; v.w *= inv;
        *(float4*)(Og + (size_t)ml * Cv + c4) = v;
    }
}

extern "C" void kernel_launch(void* const* d_in, const int* in_sizes, int n_in,
                              void* d_out, int out_size)
{
    const float* x;
    const float* adj;
    if (in_sizes[0] == BZv * Cv * Nv) {
        x   = (const float*)d_in[0];
        adj = (const float*)d_in[1];
    } else {
        x   = (const float*)d_in[1];
        adj = (const float*)d_in[0];
    }
    float* out = (float*)d_out;

    prep_A<<<2048, 256>>>(x);                                // 524288 threads
    sg_kg_tf32<<<dim3(Mv / MTm, BZv), 256>>>(adj, out);      // 32 x 8 = 256 CTAs
}